// round 12
// baseline (speedup 1.0000x reference)
#include <cuda_runtime.h>
#include <cuda_bf16.h>
#include <stdint.h>
#include <math.h>

#define EPSF 1e-8f
#define NMAX 50000
#define D1 128
#define D2 256
#define BF16_MARGIN 0.02f

typedef unsigned long long u64;

// ---------------------------------------------------------------------------
// Scratch (device globals — no allocation allowed).
// ---------------------------------------------------------------------------
__device__ float4 g_agg1_[(size_t)NMAX * D1 / 4];
__device__ float4 g_h_[(size_t)NMAX * D2 / 4];
__device__ float4 g_agg2_[(size_t)NMAX * D2 / 4];
__device__ uint4  g_xb_[(size_t)NMAX * D1 / 8];
__device__ uint4  g_hb_[(size_t)NMAX * D2 / 8];
__device__ float  g_xnorm[NMAX];
__device__ float  g_hnorm[NMAX];
__device__ int    g_is64 = 1;

// ---------------------------------------------------------------------------
// helpers
// ---------------------------------------------------------------------------
__device__ __forceinline__ unsigned pack2bf(float a, float b) {
    __nv_bfloat162 t = __floats2bfloat162_rn(a, b);
    return *(unsigned*)&t;
}
__device__ __forceinline__ uint2 pack_bf16x4(float4 v) {
    uint2 r;
    r.x = pack2bf(v.x, v.y);
    r.y = pack2bf(v.z, v.w);
    return r;
}
// packed f32x2 FMA (B300 FFMA2)
__device__ __forceinline__ u64 dup2(float a) {
    u64 r;
    asm("mov.b64 %0, {%1, %1};" : "=l"(r) : "f"(a));
    return r;
}
__device__ __forceinline__ u64 fma2(u64 a, u64 b, u64 c) {
    u64 d;
    asm("fma.rn.f32x2 %0, %1, %2, %3;" : "=l"(d) : "l"(a), "l"(b), "l"(c));
    return d;
}
__device__ __forceinline__ float2 unpk(u64 a) {
    float2 f;
    asm("mov.b64 {%0, %1}, %2;" : "=f"(f.x), "=f"(f.y) : "l"(a));
    return f;
}

// ---------------------------------------------------------------------------
// setup: edge_index dtype detection (init flag is a static initializer)
// ---------------------------------------------------------------------------
__global__ void k_reset_flag() { g_is64 = 1; }

__global__ void k_detect64(const void* __restrict__ eidx, int E, int N) {
    int i = blockIdx.x * blockDim.x + threadIdx.x;
    if (i < E) {
        long long v = ((const long long*)eidx)[i];
        if (v < 0 || v >= (long long)N) g_is64 = 0;
    }
}

// ---------------------------------------------------------------------------
// Per-node norms + self-loop init + bf16 conversion (layer-1 input x).
// ---------------------------------------------------------------------------
template<int D>
__global__ void k_norms_init(const float* __restrict__ feat,
                             float* __restrict__ norms,
                             float* __restrict__ agg,
                             uint2* __restrict__ fb, int N)
{
    int node = (blockIdx.x * blockDim.x + threadIdx.x) >> 5;
    int lane = threadIdx.x & 31;
    if (node >= N) return;
    const float4* f = (const float4*)(feat + (size_t)node * D);
    float4* a = (float4*)(agg + (size_t)node * D);
    uint2* fbr = fb + (size_t)node * (D / 4);
    float4 v[D / 128];
    float n2 = 0.f;
#pragma unroll
    for (int i = 0; i < D / 128; i++) {
        v[i] = f[lane + 32 * i];
        n2 += v[i].x * v[i].x + v[i].y * v[i].y + v[i].z * v[i].z + v[i].w * v[i].w;
    }
#pragma unroll
    for (int i = 0; i < D / 128; i++) fbr[lane + 32 * i] = pack_bf16x4(v[i]);
#pragma unroll
    for (int o = 16; o; o >>= 1) n2 += __shfl_xor_sync(0xffffffffu, n2, o);
    float nrm = sqrtf(n2);
    if (lane == 0) norms[node] = nrm;
    float denom = fmaxf(nrm * nrm, EPSF);
    bool pass = n2 > 0.5f * denom;
    float4 z = make_float4(0.f, 0.f, 0.f, 0.f);
#pragma unroll
    for (int i = 0; i < D / 128; i++) a[lane + 32 * i] = pass ? v[i] : z;
}

// ---------------------------------------------------------------------------
// Edge pass, quarter-warp per edge (8 lanes/edge, 4 edges/warp). Unchanged R11.
// ---------------------------------------------------------------------------
template<int D>
__global__ void k_edge_q(const float* __restrict__ feat,
                         const uint4* __restrict__ fb,
                         const float* __restrict__ norms,
                         const void* __restrict__ eidx,
                         float* __restrict__ agg, int E)
{
    constexpr int NSTRIDE = D / 8;
    constexpr int NCHUNK = D / 128;
    long long wid = (long long)((blockIdx.x * (unsigned)blockDim.x + threadIdx.x) >> 5);
    if (wid * 4 >= E) return;
    int lane = threadIdx.x & 31;
    int sl = lane & 7;
    long long e = wid * 4 + (lane >> 3);
    bool valid = (e < E);
    long long ec = valid ? e : (long long)E - 1;

    int s, d;
    if (g_is64) {
        const long long* p = (const long long*)eidx;
        s = (int)p[ec];
        d = (int)p[ec + E];
    } else {
        const int* p = (const int*)eidx;
        s = p[ec];
        d = p[ec + E];
    }
    float nn = norms[s] * norms[d];

    const uint4* ps = fb + (size_t)s * NSTRIDE;
    const uint4* pd = fb + (size_t)d * NSTRIDE;

    float t = 0.f;
    __nv_bfloat162 z2 = __float2bfloat162_rn(0.f);
#pragma unroll
    for (int ch = 0; ch < NCHUNK; ch++) {
        uint4 a0 = ps[sl + 16 * ch];
        uint4 a1 = ps[sl + 16 * ch + 8];
        uint4 b0 = pd[sl + 16 * ch];
        uint4 b1 = pd[sl + 16 * ch + 8];
        __nv_bfloat162 acc0 = z2, acc1 = z2;
        const __nv_bfloat162* pa0 = (const __nv_bfloat162*)&a0;
        const __nv_bfloat162* pb0 = (const __nv_bfloat162*)&b0;
        const __nv_bfloat162* pa1 = (const __nv_bfloat162*)&a1;
        const __nv_bfloat162* pb1 = (const __nv_bfloat162*)&b1;
#pragma unroll
        for (int j = 0; j < 4; j++) {
            acc0 = __hfma2(pa0[j], pb0[j], acc0);
            acc1 = __hfma2(pa1[j], pb1[j], acc1);
        }
        float2 f0 = __bfloat1622float2(acc0);
        float2 f1 = __bfloat1622float2(acc1);
        t += f0.x + f0.y + f1.x + f1.y;
    }
#pragma unroll
    for (int o = 1; o < 8; o <<= 1) t += __shfl_xor_sync(0xffffffffu, t, o);

    float thr = 0.5f * fmaxf(nn, EPSF);
    float margin = BF16_MARGIN * nn;
    bool pass;
    if (fabsf(t - thr) > margin) {
        pass = (t > thr);
    } else {
        unsigned hm = 0xFFu << (lane & 24);
        const float4* fs = (const float4*)(feat + (size_t)s * D);
        const float4* fd = (const float4*)(feat + (size_t)d * D);
        float ex = 0.f;
#pragma unroll
        for (int i = 0; i < D / 32; i++) {
            float4 av = fs[sl + 8 * i];
            float4 bv = fd[sl + 8 * i];
            ex += av.x * bv.x + av.y * bv.y + av.z * bv.z + av.w * bv.w;
        }
#pragma unroll
        for (int o = 1; o < 8; o <<= 1) ex += __shfl_xor_sync(hm, ex, o);
        pass = (ex > thr);
    }

    if (valid && pass) {
        const float4* fs = (const float4*)(feat + (size_t)s * D);
        float* out = agg + (size_t)d * D;
#pragma unroll
        for (int i = 0; i < D / 32; i++) {
            float4 av = fs[sl + 8 * i];
            asm volatile("red.global.add.v4.f32 [%0], {%1,%2,%3,%4};" ::
                         "l"(out + (sl + 8 * i) * 4),
                         "f"(av.x), "f"(av.y), "f"(av.z), "f"(av.w)
                         : "memory");
        }
    }
}

// ---------------------------------------------------------------------------
// GEMM1 (f32x2): h = relu(agg1 @ W1^T + b1). Block 64x256, K=128, 256 thr.
// As stored pre-duplicated as u64 (saves 8 ALU movs per k per thread).
// Fused epilogue: h, hb (bf16), hnorm, agg2 init.
// ---------------------------------------------------------------------------
__global__ __launch_bounds__(256)
void k_gemm1_f2(const float* __restrict__ A, const float* __restrict__ W,
                const float* __restrict__ bias,
                float* __restrict__ hq, unsigned* __restrict__ hbq,
                float* __restrict__ hnq, float* __restrict__ aggq, int M)
{
    __shared__ u64 As2[16][64];
    __shared__ float Ws[16][256];
    int tid = threadIdx.x;
    int tx = tid & 31;
    int ty = tid >> 5;
    int m0 = blockIdx.x * 64;

    u64 acc[8][4];
#pragma unroll
    for (int i = 0; i < 8; i++)
#pragma unroll
        for (int j = 0; j < 4; j++) acc[i][j] = 0ull;

    for (int k0 = 0; k0 < 128; k0 += 16) {
        {
            int m = tid >> 2, kq = tid & 3;
            int gm = m0 + m;
            if (gm >= M) gm = M - 1;
            float4 v = *(const float4*)(A + (size_t)gm * 128 + k0 + kq * 4);
            As2[kq * 4 + 0][m] = dup2(v.x);
            As2[kq * 4 + 1][m] = dup2(v.y);
            As2[kq * 4 + 2][m] = dup2(v.z);
            As2[kq * 4 + 3][m] = dup2(v.w);
        }
#pragma unroll
        for (int i = tid; i < 1024; i += 256) {
            int n = i >> 2, kq = i & 3;
            float4 v = *(const float4*)(W + (size_t)n * 128 + k0 + kq * 4);
            Ws[kq * 4 + 0][n] = v.x;
            Ws[kq * 4 + 1][n] = v.y;
            Ws[kq * 4 + 2][n] = v.z;
            Ws[kq * 4 + 3][n] = v.w;
        }
        __syncthreads();
#pragma unroll
        for (int k = 0; k < 16; k++) {
            u64 rm2[8], rn[4];
#pragma unroll
            for (int i = 0; i < 8; i++) rm2[i] = As2[k][ty * 8 + i];
#pragma unroll
            for (int j = 0; j < 4; j++)
                rn[j] = *(const u64*)&Ws[k][2 * tx + 64 * j];
#pragma unroll
            for (int i = 0; i < 8; i++)
#pragma unroll
                for (int j = 0; j < 4; j++)
                    acc[i][j] = fma2(rm2[i], rn[j], acc[i][j]);
        }
        __syncthreads();
    }

    float2 bb[4];
#pragma unroll
    for (int j = 0; j < 4; j++) bb[j] = *(const float2*)&bias[2 * tx + 64 * j];

#pragma unroll
    for (int i = 0; i < 8; i++) {
        int gm = m0 + ty * 8 + i;
        float v[8];
        float n2 = 0.f;
#pragma unroll
        for (int j = 0; j < 4; j++) {
            float2 t = unpk(acc[i][j]);
            float v0 = fmaxf(t.x + bb[j].x, 0.f);
            float v1 = fmaxf(t.y + bb[j].y, 0.f);
            v[2 * j] = v0;
            v[2 * j + 1] = v1;
            n2 += v0 * v0 + v1 * v1;
        }
#pragma unroll
        for (int o = 16; o; o >>= 1) n2 += __shfl_xor_sync(0xffffffffu, n2, o);
        bool pass = n2 > 0.5f * fmaxf(n2, EPSF);
        if (gm < M) {
            if (tx == 0) hnq[gm] = sqrtf(n2);
            float2 z2 = make_float2(0.f, 0.f);
#pragma unroll
            for (int j = 0; j < 4; j++) {
                float2 hv = make_float2(v[2 * j], v[2 * j + 1]);
                *(float2*)(hq + (size_t)gm * 256 + 2 * tx + 64 * j) = hv;
                *(float2*)(aggq + (size_t)gm * 256 + 2 * tx + 64 * j) = pass ? hv : z2;
                hbq[(size_t)gm * 128 + tx + 32 * j] = pack2bf(hv.x, hv.y);
            }
        }
    }
}

// ---------------------------------------------------------------------------
// GEMM2 (f32x2): out = log_softmax(agg2 @ W2^T + b2). Block 128x64, K=256.
// As pre-duplicated u64.
// ---------------------------------------------------------------------------
__global__ __launch_bounds__(256)
void k_gemm2_f2(const float* __restrict__ A, const float* __restrict__ W,
                const float* __restrict__ bias,
                float* __restrict__ outq, int M)
{
    __shared__ u64 As2[16][128];
    __shared__ float Ws[16][64];
    int tid = threadIdx.x;
    int tx = tid & 15;
    int ty = tid >> 4;
    int m0 = blockIdx.x * 128;

    u64 acc[8][2];
#pragma unroll
    for (int i = 0; i < 8; i++) {
        acc[i][0] = 0ull;
        acc[i][1] = 0ull;
    }

    for (int k0 = 0; k0 < 256; k0 += 16) {
#pragma unroll
        for (int i = tid; i < 512; i += 256) {
            int m = i >> 2, kq = i & 3;
            int gm = m0 + m;
            if (gm >= M) gm = M - 1;
            float4 v = *(const float4*)(A + (size_t)gm * 256 + k0 + kq * 4);
            As2[kq * 4 + 0][m] = dup2(v.x);
            As2[kq * 4 + 1][m] = dup2(v.y);
            As2[kq * 4 + 2][m] = dup2(v.z);
            As2[kq * 4 + 3][m] = dup2(v.w);
        }
        {
            int n = tid >> 2, kq = tid & 3;
            float4 v = *(const float4*)(W + (size_t)n * 256 + k0 + kq * 4);
            Ws[kq * 4 + 0][n] = v.x;
            Ws[kq * 4 + 1][n] = v.y;
            Ws[kq * 4 + 2][n] = v.z;
            Ws[kq * 4 + 3][n] = v.w;
        }
        __syncthreads();
#pragma unroll
        for (int k = 0; k < 16; k++) {
            u64 rm2[8], rn[2];
#pragma unroll
            for (int i = 0; i < 8; i++) rm2[i] = As2[k][ty * 8 + i];
            rn[0] = *(const u64*)&Ws[k][2 * tx];
            rn[1] = *(const u64*)&Ws[k][2 * tx + 32];
#pragma unroll
            for (int i = 0; i < 8; i++) {
                acc[i][0] = fma2(rm2[i], rn[0], acc[i][0]);
                acc[i][1] = fma2(rm2[i], rn[1], acc[i][1]);
            }
        }
        __syncthreads();
    }

    float2 bb0 = *(const float2*)&bias[2 * tx];
    float2 bb1 = *(const float2*)&bias[2 * tx + 32];

#pragma unroll
    for (int i = 0; i < 8; i++) {
        int gm = m0 + ty * 8 + i;
        float2 t0 = unpk(acc[i][0]);
        float2 t1 = unpk(acc[i][1]);
        float v0 = t0.x + bb0.x, v1 = t0.y + bb0.y;
        float v2 = t1.x + bb1.x, v3 = t1.y + bb1.y;
        float mx = fmaxf(fmaxf(v0, v1), fmaxf(v2, v3));
#pragma unroll
        for (int o = 1; o < 16; o <<= 1)
            mx = fmaxf(mx, __shfl_xor_sync(0xffffffffu, mx, o));
        float sm = __expf(v0 - mx) + __expf(v1 - mx) +
                   __expf(v2 - mx) + __expf(v3 - mx);
#pragma unroll
        for (int o = 1; o < 16; o <<= 1)
            sm += __shfl_xor_sync(0xffffffffu, sm, o);
        float l = mx + __logf(sm);
        if (gm < M) {
            *(float2*)(outq + (size_t)gm * 64 + 2 * tx) = make_float2(v0 - l, v1 - l);
            *(float2*)(outq + (size_t)gm * 64 + 2 * tx + 32) = make_float2(v2 - l, v3 - l);
        }
    }
}

// ---------------------------------------------------------------------------
extern "C" void kernel_launch(void* const* d_in, const int* in_sizes, int n_in,
                              void* d_out, int out_size)
{
    const float* x   = (const float*)d_in[0];
    const void*  eix = d_in[1];
    const float* W1  = (const float*)d_in[2];
    const float* b1  = (const float*)d_in[3];
    const float* W2  = (const float*)d_in[4];
    const float* b2  = (const float*)d_in[5];
    float* out = (float*)d_out;

    int N = in_sizes[0] / D1;      // 50000
    int E = in_sizes[1] / 2;       // 800000
    (void)n_in; (void)out_size;

    float *agg1, *h, *agg2, *xn, *hn;
    uint4 *xb, *hb;
    cudaGetSymbolAddress((void**)&agg1, g_agg1_);
    cudaGetSymbolAddress((void**)&h,    g_h_);
    cudaGetSymbolAddress((void**)&agg2, g_agg2_);
    cudaGetSymbolAddress((void**)&xb,   g_xb_);
    cudaGetSymbolAddress((void**)&hb,   g_hb_);
    cudaGetSymbolAddress((void**)&xn,   g_xnorm);
    cudaGetSymbolAddress((void**)&hn,   g_hnorm);

    k_reset_flag<<<1, 1>>>();
    k_detect64<<<(E + 255) / 256, 256>>>(eix, E, N);

    int nodeBlocks = (N * 32 + 255) / 256;
    long long warps4 = ((long long)E + 3) / 4;
    int edgeBlocks = (int)((warps4 * 32 + 255) / 256);

    // ---- Layer 1 ----
    k_norms_init<D1><<<nodeBlocks, 256>>>(x, xn, agg1, (uint2*)xb, N);
    k_edge_q<D1><<<edgeBlocks, 256>>>(x, xb, xn, eix, agg1, E);
    k_gemm1_f2<<<(N + 63) / 64, 256>>>(agg1, W1, b1, h, (unsigned*)hb, hn, agg2, N);

    // ---- Layer 2 ----
    k_edge_q<D2><<<edgeBlocks, 256>>>(h, hb, hn, eix, agg2, E);
    k_gemm2_f2<<<(N + 127) / 128, 256>>>(agg2, W2, b2, out, N);
}

// round 13
// speedup vs baseline: 1.1415x; 1.1415x over previous
#include <cuda_runtime.h>
#include <cuda_bf16.h>
#include <stdint.h>
#include <math.h>

#define EPSF 1e-8f
#define NMAX 50000
#define D1 128
#define D2 256
#define BF16_MARGIN 0.02f

typedef unsigned long long u64;

// ---------------------------------------------------------------------------
// Scratch (device globals — no allocation allowed).
// ---------------------------------------------------------------------------
__device__ float4 g_agg1_[(size_t)NMAX * D1 / 4];
__device__ float4 g_h_[(size_t)NMAX * D2 / 4];
__device__ float4 g_agg2_[(size_t)NMAX * D2 / 4];
__device__ uint4  g_xb_[(size_t)NMAX * D1 / 8];
__device__ uint4  g_hb_[(size_t)NMAX * D2 / 8];
__device__ float  g_xnorm[NMAX];
__device__ float  g_hnorm[NMAX];
__device__ int    g_is64;

// ---------------------------------------------------------------------------
// helpers
// ---------------------------------------------------------------------------
__device__ __forceinline__ unsigned pack2bf(float a, float b) {
    __nv_bfloat162 t = __floats2bfloat162_rn(a, b);
    return *(unsigned*)&t;
}
__device__ __forceinline__ uint2 pack_bf16x4(float4 v) {
    uint2 r;
    r.x = pack2bf(v.x, v.y);
    r.y = pack2bf(v.z, v.w);
    return r;
}
// packed f32x2 FMA (B300 FFMA2)
__device__ __forceinline__ u64 dup2(float a) {
    u64 r;
    asm("mov.b64 %0, {%1, %1};" : "=l"(r) : "f"(a));
    return r;
}
__device__ __forceinline__ u64 fma2(u64 a, u64 b, u64 c) {
    u64 d;
    asm("fma.rn.f32x2 %0, %1, %2, %3;" : "=l"(d) : "l"(a), "l"(b), "l"(c));
    return d;
}
__device__ __forceinline__ float2 unpk(u64 a) {
    float2 f;
    asm("mov.b64 {%0, %1}, %2;" : "=f"(f.x), "=f"(f.y) : "l"(a));
    return f;
}

// ---------------------------------------------------------------------------
// setup kernels
// ---------------------------------------------------------------------------
__global__ void k_reset_flag() { g_is64 = 1; }

__global__ void k_detect64(const void* __restrict__ eidx, int E, int N) {
    int i = blockIdx.x * blockDim.x + threadIdx.x;
    if (i < E) {
        long long v = ((const long long*)eidx)[i];
        if (v < 0 || v >= (long long)N) g_is64 = 0;
    }
}

// ---------------------------------------------------------------------------
// Per-node norms + self-loop init + bf16 conversion (layer-1 input x).
// ---------------------------------------------------------------------------
template<int D>
__global__ void k_norms_init(const float* __restrict__ feat,
                             float* __restrict__ norms,
                             float* __restrict__ agg,
                             uint2* __restrict__ fb, int N)
{
    int node = (blockIdx.x * blockDim.x + threadIdx.x) >> 5;
    int lane = threadIdx.x & 31;
    if (node >= N) return;
    const float4* f = (const float4*)(feat + (size_t)node * D);
    float4* a = (float4*)(agg + (size_t)node * D);
    uint2* fbr = fb + (size_t)node * (D / 4);
    float4 v[D / 128];
    float n2 = 0.f;
#pragma unroll
    for (int i = 0; i < D / 128; i++) {
        v[i] = f[lane + 32 * i];
        n2 += v[i].x * v[i].x + v[i].y * v[i].y + v[i].z * v[i].z + v[i].w * v[i].w;
    }
#pragma unroll
    for (int i = 0; i < D / 128; i++) fbr[lane + 32 * i] = pack_bf16x4(v[i]);
#pragma unroll
    for (int o = 16; o; o >>= 1) n2 += __shfl_xor_sync(0xffffffffu, n2, o);
    float nrm = sqrtf(n2);
    if (lane == 0) norms[node] = nrm;
    float denom = fmaxf(nrm * nrm, EPSF);
    bool pass = n2 > 0.5f * denom;
    float4 z = make_float4(0.f, 0.f, 0.f, 0.f);
#pragma unroll
    for (int i = 0; i < D / 128; i++) a[lane + 32 * i] = pass ? v[i] : z;
}

// ---------------------------------------------------------------------------
// Edge pass, quarter-warp per edge (8 lanes/edge, 4 edges/warp). Unchanged R11.
// ---------------------------------------------------------------------------
template<int D>
__global__ void k_edge_q(const float* __restrict__ feat,
                         const uint4* __restrict__ fb,
                         const float* __restrict__ norms,
                         const void* __restrict__ eidx,
                         float* __restrict__ agg, int E)
{
    constexpr int NSTRIDE = D / 8;
    constexpr int NCHUNK = D / 128;
    long long wid = (long long)((blockIdx.x * (unsigned)blockDim.x + threadIdx.x) >> 5);
    if (wid * 4 >= E) return;
    int lane = threadIdx.x & 31;
    int sl = lane & 7;
    long long e = wid * 4 + (lane >> 3);
    bool valid = (e < E);
    long long ec = valid ? e : (long long)E - 1;

    int s, d;
    if (g_is64) {
        const long long* p = (const long long*)eidx;
        s = (int)p[ec];
        d = (int)p[ec + E];
    } else {
        const int* p = (const int*)eidx;
        s = p[ec];
        d = p[ec + E];
    }
    float nn = norms[s] * norms[d];

    const uint4* ps = fb + (size_t)s * NSTRIDE;
    const uint4* pd = fb + (size_t)d * NSTRIDE;

    float t = 0.f;
    __nv_bfloat162 z2 = __float2bfloat162_rn(0.f);
#pragma unroll
    for (int ch = 0; ch < NCHUNK; ch++) {
        uint4 a0 = ps[sl + 16 * ch];
        uint4 a1 = ps[sl + 16 * ch + 8];
        uint4 b0 = pd[sl + 16 * ch];
        uint4 b1 = pd[sl + 16 * ch + 8];
        __nv_bfloat162 acc0 = z2, acc1 = z2;
        const __nv_bfloat162* pa0 = (const __nv_bfloat162*)&a0;
        const __nv_bfloat162* pb0 = (const __nv_bfloat162*)&b0;
        const __nv_bfloat162* pa1 = (const __nv_bfloat162*)&a1;
        const __nv_bfloat162* pb1 = (const __nv_bfloat162*)&b1;
#pragma unroll
        for (int j = 0; j < 4; j++) {
            acc0 = __hfma2(pa0[j], pb0[j], acc0);
            acc1 = __hfma2(pa1[j], pb1[j], acc1);
        }
        float2 f0 = __bfloat1622float2(acc0);
        float2 f1 = __bfloat1622float2(acc1);
        t += f0.x + f0.y + f1.x + f1.y;
    }
#pragma unroll
    for (int o = 1; o < 8; o <<= 1) t += __shfl_xor_sync(0xffffffffu, t, o);

    float thr = 0.5f * fmaxf(nn, EPSF);
    float margin = BF16_MARGIN * nn;
    bool pass;
    if (fabsf(t - thr) > margin) {
        pass = (t > thr);
    } else {
        unsigned hm = 0xFFu << (lane & 24);
        const float4* fs = (const float4*)(feat + (size_t)s * D);
        const float4* fd = (const float4*)(feat + (size_t)d * D);
        float ex = 0.f;
#pragma unroll
        for (int i = 0; i < D / 32; i++) {
            float4 av = fs[sl + 8 * i];
            float4 bv = fd[sl + 8 * i];
            ex += av.x * bv.x + av.y * bv.y + av.z * bv.z + av.w * bv.w;
        }
#pragma unroll
        for (int o = 1; o < 8; o <<= 1) ex += __shfl_xor_sync(hm, ex, o);
        pass = (ex > thr);
    }

    if (valid && pass) {
        const float4* fs = (const float4*)(feat + (size_t)s * D);
        float* out = agg + (size_t)d * D;
#pragma unroll
        for (int i = 0; i < D / 32; i++) {
            float4 av = fs[sl + 8 * i];
            asm volatile("red.global.add.v4.f32 [%0], {%1,%2,%3,%4};" ::
                         "l"(out + (sl + 8 * i) * 4),
                         "f"(av.x), "f"(av.y), "f"(av.z), "f"(av.w)
                         : "memory");
        }
    }
}

// ---------------------------------------------------------------------------
// GEMM1 (f32x2, R11 layout + prefetch pipeline): h = relu(agg1 @ W1^T + b1).
// Block 64x256, K=128, 256 thr. Conflict-free cols {2tx,2tx+1}+64j.
// Fused epilogue: h, hb (bf16), hnorm, agg2 init.
// ---------------------------------------------------------------------------
__global__ __launch_bounds__(256)
void k_gemm1_f2(const float* __restrict__ A, const float* __restrict__ W,
                const float* __restrict__ bias,
                float* __restrict__ hq, unsigned* __restrict__ hbq,
                float* __restrict__ hnq, float* __restrict__ aggq, int M)
{
    __shared__ float As[16][64];
    __shared__ float Ws[16][256];
    int tid = threadIdx.x;
    int tx = tid & 31;
    int ty = tid >> 5;
    int m0 = blockIdx.x * 64;

    int lm = tid >> 2, lkq = tid & 3;     // A-load role
    int lgm = m0 + lm;
    if (lgm >= M) lgm = M - 1;
    const float* Arow = A + (size_t)lgm * 128 + lkq * 4;
    const float* Wbase = W + (size_t)lm * 128 + lkq * 4;  // rows lm, lm+64, lm+128, lm+192

    u64 acc[8][4];
#pragma unroll
    for (int i = 0; i < 8; i++)
#pragma unroll
        for (int j = 0; j < 4; j++) acc[i][j] = 0ull;

    // prefetch k0 = 0
    float4 va = *(const float4*)Arow;
    float4 vw[4];
#pragma unroll
    for (int j = 0; j < 4; j++)
        vw[j] = *(const float4*)(Wbase + (size_t)j * 64 * 128);

    for (int k0 = 0; k0 < 128; k0 += 16) {
        As[lkq * 4 + 0][lm] = va.x;
        As[lkq * 4 + 1][lm] = va.y;
        As[lkq * 4 + 2][lm] = va.z;
        As[lkq * 4 + 3][lm] = va.w;
#pragma unroll
        for (int j = 0; j < 4; j++) {
            int n = lm + 64 * j;
            Ws[lkq * 4 + 0][n] = vw[j].x;
            Ws[lkq * 4 + 1][n] = vw[j].y;
            Ws[lkq * 4 + 2][n] = vw[j].z;
            Ws[lkq * 4 + 3][n] = vw[j].w;
        }
        __syncthreads();
        if (k0 + 16 < 128) {
            va = *(const float4*)(Arow + k0 + 16);
#pragma unroll
            for (int j = 0; j < 4; j++)
                vw[j] = *(const float4*)(Wbase + (size_t)j * 64 * 128 + k0 + 16);
        }
#pragma unroll
        for (int k = 0; k < 16; k++) {
            u64 rm2[8], rn[4];
#pragma unroll
            for (int i = 0; i < 8; i++) rm2[i] = dup2(As[k][ty * 8 + i]);
#pragma unroll
            for (int j = 0; j < 4; j++)
                rn[j] = *(const u64*)&Ws[k][2 * tx + 64 * j];
#pragma unroll
            for (int i = 0; i < 8; i++)
#pragma unroll
                for (int j = 0; j < 4; j++)
                    acc[i][j] = fma2(rm2[i], rn[j], acc[i][j]);
        }
        __syncthreads();
    }

    float2 bb[4];
#pragma unroll
    for (int j = 0; j < 4; j++) bb[j] = *(const float2*)&bias[2 * tx + 64 * j];

#pragma unroll
    for (int i = 0; i < 8; i++) {
        int gm = m0 + ty * 8 + i;
        float v[8];
        float n2 = 0.f;
#pragma unroll
        for (int j = 0; j < 4; j++) {
            float2 t = unpk(acc[i][j]);
            float v0 = fmaxf(t.x + bb[j].x, 0.f);
            float v1 = fmaxf(t.y + bb[j].y, 0.f);
            v[2 * j] = v0;
            v[2 * j + 1] = v1;
            n2 += v0 * v0 + v1 * v1;
        }
#pragma unroll
        for (int o = 16; o; o >>= 1) n2 += __shfl_xor_sync(0xffffffffu, n2, o);
        bool pass = n2 > 0.5f * fmaxf(n2, EPSF);
        if (gm < M) {
            if (tx == 0) hnq[gm] = sqrtf(n2);
            float2 z2 = make_float2(0.f, 0.f);
#pragma unroll
            for (int j = 0; j < 4; j++) {
                float2 hv = make_float2(v[2 * j], v[2 * j + 1]);
                *(float2*)(hq + (size_t)gm * 256 + 2 * tx + 64 * j) = hv;
                *(float2*)(aggq + (size_t)gm * 256 + 2 * tx + 64 * j) = pass ? hv : z2;
                hbq[(size_t)gm * 128 + tx + 32 * j] = pack2bf(hv.x, hv.y);
            }
        }
    }
}

// ---------------------------------------------------------------------------
// GEMM2 (f32x2, R11 layout + prefetch pipeline): out = log_softmax(...).
// Block 128x64, K=256, 256 thr.
// ---------------------------------------------------------------------------
__global__ __launch_bounds__(256)
void k_gemm2_f2(const float* __restrict__ A, const float* __restrict__ W,
                const float* __restrict__ bias,
                float* __restrict__ outq, int M)
{
    __shared__ float As[16][128];
    __shared__ float Ws[16][64];
    int tid = threadIdx.x;
    int tx = tid & 15;
    int ty = tid >> 4;
    int m0 = blockIdx.x * 128;

    int lm = tid >> 2, lkq = tid & 3;
    int lgm0 = m0 + lm;
    if (lgm0 >= M) lgm0 = M - 1;
    int lgm1 = m0 + lm + 64;
    if (lgm1 >= M) lgm1 = M - 1;
    const float* Arow0 = A + (size_t)lgm0 * 256 + lkq * 4;
    const float* Arow1 = A + (size_t)lgm1 * 256 + lkq * 4;
    const float* Wrow = W + (size_t)lm * 256 + lkq * 4;

    u64 acc[8][2];
#pragma unroll
    for (int i = 0; i < 8; i++) {
        acc[i][0] = 0ull;
        acc[i][1] = 0ull;
    }

    float4 va0 = *(const float4*)Arow0;
    float4 va1 = *(const float4*)Arow1;
    float4 vw = *(const float4*)Wrow;

    for (int k0 = 0; k0 < 256; k0 += 16) {
        As[lkq * 4 + 0][lm] = va0.x;
        As[lkq * 4 + 1][lm] = va0.y;
        As[lkq * 4 + 2][lm] = va0.z;
        As[lkq * 4 + 3][lm] = va0.w;
        As[lkq * 4 + 0][lm + 64] = va1.x;
        As[lkq * 4 + 1][lm + 64] = va1.y;
        As[lkq * 4 + 2][lm + 64] = va1.z;
        As[lkq * 4 + 3][lm + 64] = va1.w;
        Ws[lkq * 4 + 0][lm] = vw.x;
        Ws[lkq * 4 + 1][lm] = vw.y;
        Ws[lkq * 4 + 2][lm] = vw.z;
        Ws[lkq * 4 + 3][lm] = vw.w;
        __syncthreads();
        if (k0 + 16 < 256) {
            va0 = *(const float4*)(Arow0 + k0 + 16);
            va1 = *(const float4*)(Arow1 + k0 + 16);
            vw = *(const float4*)(Wrow + k0 + 16);
        }
#pragma unroll
        for (int k = 0; k < 16; k++) {
            u64 rm2[8], rn[2];
#pragma unroll
            for (int i = 0; i < 8; i++) rm2[i] = dup2(As[k][ty * 8 + i]);
            rn[0] = *(const u64*)&Ws[k][2 * tx];
            rn[1] = *(const u64*)&Ws[k][2 * tx + 32];
#pragma unroll
            for (int i = 0; i < 8; i++) {
                acc[i][0] = fma2(rm2[i], rn[0], acc[i][0]);
                acc[i][1] = fma2(rm2[i], rn[1], acc[i][1]);
            }
        }
        __syncthreads();
    }

    float2 bb0 = *(const float2*)&bias[2 * tx];
    float2 bb1 = *(const float2*)&bias[2 * tx + 32];

#pragma unroll
    for (int i = 0; i < 8; i++) {
        int gm = m0 + ty * 8 + i;
        float2 t0 = unpk(acc[i][0]);
        float2 t1 = unpk(acc[i][1]);
        float v0 = t0.x + bb0.x, v1 = t0.y + bb0.y;
        float v2 = t1.x + bb1.x, v3 = t1.y + bb1.y;
        float mx = fmaxf(fmaxf(v0, v1), fmaxf(v2, v3));
#pragma unroll
        for (int o = 1; o < 16; o <<= 1)
            mx = fmaxf(mx, __shfl_xor_sync(0xffffffffu, mx, o));
        float sm = __expf(v0 - mx) + __expf(v1 - mx) +
                   __expf(v2 - mx) + __expf(v3 - mx);
#pragma unroll
        for (int o = 1; o < 16; o <<= 1)
            sm += __shfl_xor_sync(0xffffffffu, sm, o);
        float l = mx + __logf(sm);
        if (gm < M) {
            *(float2*)(outq + (size_t)gm * 64 + 2 * tx) = make_float2(v0 - l, v1 - l);
            *(float2*)(outq + (size_t)gm * 64 + 2 * tx + 32) = make_float2(v2 - l, v3 - l);
        }
    }
}

// ---------------------------------------------------------------------------
extern "C" void kernel_launch(void* const* d_in, const int* in_sizes, int n_in,
                              void* d_out, int out_size)
{
    const float* x   = (const float*)d_in[0];
    const void*  eix = d_in[1];
    const float* W1  = (const float*)d_in[2];
    const float* b1  = (const float*)d_in[3];
    const float* W2  = (const float*)d_in[4];
    const float* b2  = (const float*)d_in[5];
    float* out = (float*)d_out;

    int N = in_sizes[0] / D1;      // 50000
    int E = in_sizes[1] / 2;       // 800000
    (void)n_in; (void)out_size;

    float *agg1, *h, *agg2, *xn, *hn;
    uint4 *xb, *hb;
    cudaGetSymbolAddress((void**)&agg1, g_agg1_);
    cudaGetSymbolAddress((void**)&h,    g_h_);
    cudaGetSymbolAddress((void**)&agg2, g_agg2_);
    cudaGetSymbolAddress((void**)&xb,   g_xb_);
    cudaGetSymbolAddress((void**)&hb,   g_hb_);
    cudaGetSymbolAddress((void**)&xn,   g_xnorm);
    cudaGetSymbolAddress((void**)&hn,   g_hnorm);

    k_reset_flag<<<1, 1>>>();
    k_detect64<<<(E + 255) / 256, 256>>>(eix, E, N);

    int nodeBlocks = (N * 32 + 255) / 256;
    long long warps4 = ((long long)E + 3) / 4;
    int edgeBlocks = (int)((warps4 * 32 + 255) / 256);

    // ---- Layer 1 ----
    k_norms_init<D1><<<nodeBlocks, 256>>>(x, xn, agg1, (uint2*)xb, N);
    k_edge_q<D1><<<edgeBlocks, 256>>>(x, xb, xn, eix, agg1, E);
    k_gemm1_f2<<<(N + 63) / 64, 256>>>(agg1, W1, b1, h, (unsigned*)hb, hn, agg2, N);

    // ---- Layer 2 ----
    k_edge_q<D2><<<edgeBlocks, 256>>>(h, hb, hn, eix, agg2, E);
    k_gemm2_f2<<<(N + 127) / 128, 256>>>(agg2, W2, b2, out, N);
}

// round 14
// speedup vs baseline: 1.1582x; 1.0146x over previous
#include <cuda_runtime.h>
#include <cuda_bf16.h>
#include <stdint.h>
#include <math.h>

#define EPSF 1e-8f
#define NMAX 50000
#define D1 128
#define D2 256
// normalized bf16 + HFMA2-chain dot: |t - sim| <= 2^-6 = 0.0156 < 0.02
#define BF16_MARGIN 0.02f

typedef unsigned long long u64;

// ---------------------------------------------------------------------------
// Scratch (device globals — no allocation allowed).
// ---------------------------------------------------------------------------
__device__ float4 g_agg1_[(size_t)NMAX * D1 / 4];
__device__ float4 g_h_[(size_t)NMAX * D2 / 4];
__device__ float4 g_agg2_[(size_t)NMAX * D2 / 4];
__device__ uint4  g_xb_[(size_t)NMAX * D1 / 8];   // bf16 x / ||x||
__device__ uint4  g_hb_[(size_t)NMAX * D2 / 8];   // bf16 h / ||h||
__device__ float  g_xnorm[NMAX];
__device__ float  g_hnorm[NMAX];
__device__ int    g_is64;

// ---------------------------------------------------------------------------
// helpers
// ---------------------------------------------------------------------------
__device__ __forceinline__ unsigned pack2bf(float a, float b) {
    __nv_bfloat162 t = __floats2bfloat162_rn(a, b);
    return *(unsigned*)&t;
}
// packed f32x2 FMA (B300 FFMA2)
__device__ __forceinline__ u64 dup2(float a) {
    u64 r;
    asm("mov.b64 %0, {%1, %1};" : "=l"(r) : "f"(a));
    return r;
}
__device__ __forceinline__ u64 fma2(u64 a, u64 b, u64 c) {
    u64 d;
    asm("fma.rn.f32x2 %0, %1, %2, %3;" : "=l"(d) : "l"(a), "l"(b), "l"(c));
    return d;
}
__device__ __forceinline__ float2 unpk(u64 a) {
    float2 f;
    asm("mov.b64 {%0, %1}, %2;" : "=f"(f.x), "=f"(f.y) : "l"(a));
    return f;
}

// ---------------------------------------------------------------------------
// setup kernels
// ---------------------------------------------------------------------------
__global__ void k_reset_flag() { g_is64 = 1; }

__global__ void k_detect64(const void* __restrict__ eidx, int E, int N) {
    int i = blockIdx.x * blockDim.x + threadIdx.x;
    if (i < E) {
        long long v = ((const long long*)eidx)[i];
        if (v < 0 || v >= (long long)N) g_is64 = 0;
    }
}

// ---------------------------------------------------------------------------
// Per-node norms + self-loop init + NORMALIZED bf16 conversion (layer-1 x).
// ---------------------------------------------------------------------------
template<int D>
__global__ void k_norms_init(const float* __restrict__ feat,
                             float* __restrict__ norms,
                             float* __restrict__ agg,
                             uint2* __restrict__ fb, int N)
{
    int node = (blockIdx.x * blockDim.x + threadIdx.x) >> 5;
    int lane = threadIdx.x & 31;
    if (node >= N) return;
    const float4* f = (const float4*)(feat + (size_t)node * D);
    float4* a = (float4*)(agg + (size_t)node * D);
    uint2* fbr = fb + (size_t)node * (D / 4);
    float4 v[D / 128];
    float n2 = 0.f;
#pragma unroll
    for (int i = 0; i < D / 128; i++) {
        v[i] = f[lane + 32 * i];
        n2 += v[i].x * v[i].x + v[i].y * v[i].y + v[i].z * v[i].z + v[i].w * v[i].w;
    }
#pragma unroll
    for (int o = 16; o; o >>= 1) n2 += __shfl_xor_sync(0xffffffffu, n2, o);
    float nrm = sqrtf(n2);
    if (lane == 0) norms[node] = nrm;
    float sc = (nrm > 0.f) ? 1.f / nrm : 0.f;
#pragma unroll
    for (int i = 0; i < D / 128; i++) {
        uint2 r;
        r.x = pack2bf(v[i].x * sc, v[i].y * sc);
        r.y = pack2bf(v[i].z * sc, v[i].w * sc);
        fbr[lane + 32 * i] = r;
    }
    float denom = fmaxf(nrm * nrm, EPSF);
    bool pass = n2 > 0.5f * denom;
    float4 z = make_float4(0.f, 0.f, 0.f, 0.f);
#pragma unroll
    for (int i = 0; i < D / 128; i++) a[lane + 32 * i] = pass ? v[i] : z;
}

// ---------------------------------------------------------------------------
// Edge pass, quarter-warp per edge. Features pre-normalized -> sim = dot,
// threshold constant 0.5. norms only touched on the rare rescue path.
// ---------------------------------------------------------------------------
template<int D>
__global__ void k_edge_q(const float* __restrict__ feat,
                         const uint4* __restrict__ fb,
                         const float* __restrict__ norms,
                         const void* __restrict__ eidx,
                         float* __restrict__ agg, int E)
{
    constexpr int NSTRIDE = D / 8;
    constexpr int NCHUNK = D / 128;
    long long wid = (long long)((blockIdx.x * (unsigned)blockDim.x + threadIdx.x) >> 5);
    if (wid * 4 >= E) return;
    int lane = threadIdx.x & 31;
    int sl = lane & 7;
    long long e = wid * 4 + (lane >> 3);
    bool valid = (e < E);
    long long ec = valid ? e : (long long)E - 1;

    int s, d;
    if (g_is64) {
        const long long* p = (const long long*)eidx;
        s = (int)p[ec];
        d = (int)p[ec + E];
    } else {
        const int* p = (const int*)eidx;
        s = p[ec];
        d = p[ec + E];
    }

    const uint4* ps = fb + (size_t)s * NSTRIDE;
    const uint4* pd = fb + (size_t)d * NSTRIDE;

    float t = 0.f;
    __nv_bfloat162 z2 = __float2bfloat162_rn(0.f);
#pragma unroll
    for (int ch = 0; ch < NCHUNK; ch++) {
        uint4 a0 = ps[sl + 16 * ch];
        uint4 a1 = ps[sl + 16 * ch + 8];
        uint4 b0 = pd[sl + 16 * ch];
        uint4 b1 = pd[sl + 16 * ch + 8];
        __nv_bfloat162 acc0 = z2, acc1 = z2;
        const __nv_bfloat162* pa0 = (const __nv_bfloat162*)&a0;
        const __nv_bfloat162* pb0 = (const __nv_bfloat162*)&b0;
        const __nv_bfloat162* pa1 = (const __nv_bfloat162*)&a1;
        const __nv_bfloat162* pb1 = (const __nv_bfloat162*)&b1;
#pragma unroll
        for (int j = 0; j < 4; j++) {
            acc0 = __hfma2(pa0[j], pb0[j], acc0);
            acc1 = __hfma2(pa1[j], pb1[j], acc1);
        }
        float2 f0 = __bfloat1622float2(acc0);
        float2 f1 = __bfloat1622float2(acc1);
        t += f0.x + f0.y + f1.x + f1.y;
    }
#pragma unroll
    for (int o = 1; o < 8; o <<= 1) t += __shfl_xor_sync(0xffffffffu, t, o);

    bool pass;
    if (fabsf(t - 0.5f) > BF16_MARGIN) {
        pass = (t > 0.5f);
    } else {
        // rescue: exact fp32 reference comparison (rare; group-uniform branch)
        unsigned hm = 0xFFu << (lane & 24);
        float nn = norms[s] * norms[d];
        const float4* fs = (const float4*)(feat + (size_t)s * D);
        const float4* fd = (const float4*)(feat + (size_t)d * D);
        float ex = 0.f;
#pragma unroll
        for (int i = 0; i < D / 32; i++) {
            float4 av = fs[sl + 8 * i];
            float4 bv = fd[sl + 8 * i];
            ex += av.x * bv.x + av.y * bv.y + av.z * bv.z + av.w * bv.w;
        }
#pragma unroll
        for (int o = 1; o < 8; o <<= 1) ex += __shfl_xor_sync(hm, ex, o);
        pass = (ex > 0.5f * fmaxf(nn, EPSF));
    }

    if (valid && pass) {
        const float4* fs = (const float4*)(feat + (size_t)s * D);
        float* out = agg + (size_t)d * D;
#pragma unroll
        for (int i = 0; i < D / 32; i++) {
            float4 av = fs[sl + 8 * i];
            asm volatile("red.global.add.v4.f32 [%0], {%1,%2,%3,%4};" ::
                         "l"(out + (sl + 8 * i) * 4),
                         "f"(av.x), "f"(av.y), "f"(av.z), "f"(av.w)
                         : "memory");
        }
    }
}

// ---------------------------------------------------------------------------
// GEMM1 (f32x2 + prefetch): h = relu(agg1 @ W1^T + b1). Block 64x256, K=128.
// Fused epilogue: h, hb (NORMALIZED bf16), hnorm, agg2 init.
// ---------------------------------------------------------------------------
__global__ __launch_bounds__(256)
void k_gemm1_f2(const float* __restrict__ A, const float* __restrict__ W,
                const float* __restrict__ bias,
                float* __restrict__ hq, unsigned* __restrict__ hbq,
                float* __restrict__ hnq, float* __restrict__ aggq, int M)
{
    __shared__ float As[16][64];
    __shared__ float Ws[16][256];
    int tid = threadIdx.x;
    int tx = tid & 31;
    int ty = tid >> 5;
    int m0 = blockIdx.x * 64;

    int lm = tid >> 2, lkq = tid & 3;
    int lgm = m0 + lm;
    if (lgm >= M) lgm = M - 1;
    const float* Arow = A + (size_t)lgm * 128 + lkq * 4;
    const float* Wbase = W + (size_t)lm * 128 + lkq * 4;

    u64 acc[8][4];
#pragma unroll
    for (int i = 0; i < 8; i++)
#pragma unroll
        for (int j = 0; j < 4; j++) acc[i][j] = 0ull;

    float4 va = *(const float4*)Arow;
    float4 vw[4];
#pragma unroll
    for (int j = 0; j < 4; j++)
        vw[j] = *(const float4*)(Wbase + (size_t)j * 64 * 128);

    for (int k0 = 0; k0 < 128; k0 += 16) {
        As[lkq * 4 + 0][lm] = va.x;
        As[lkq * 4 + 1][lm] = va.y;
        As[lkq * 4 + 2][lm] = va.z;
        As[lkq * 4 + 3][lm] = va.w;
#pragma unroll
        for (int j = 0; j < 4; j++) {
            int n = lm + 64 * j;
            Ws[lkq * 4 + 0][n] = vw[j].x;
            Ws[lkq * 4 + 1][n] = vw[j].y;
            Ws[lkq * 4 + 2][n] = vw[j].z;
            Ws[lkq * 4 + 3][n] = vw[j].w;
        }
        __syncthreads();
        if (k0 + 16 < 128) {
            va = *(const float4*)(Arow + k0 + 16);
#pragma unroll
            for (int j = 0; j < 4; j++)
                vw[j] = *(const float4*)(Wbase + (size_t)j * 64 * 128 + k0 + 16);
        }
#pragma unroll
        for (int k = 0; k < 16; k++) {
            u64 rm2[8], rn[4];
#pragma unroll
            for (int i = 0; i < 8; i++) rm2[i] = dup2(As[k][ty * 8 + i]);
#pragma unroll
            for (int j = 0; j < 4; j++)
                rn[j] = *(const u64*)&Ws[k][2 * tx + 64 * j];
#pragma unroll
            for (int i = 0; i < 8; i++)
#pragma unroll
                for (int j = 0; j < 4; j++)
                    acc[i][j] = fma2(rm2[i], rn[j], acc[i][j]);
        }
        __syncthreads();
    }

    float2 bb[4];
#pragma unroll
    for (int j = 0; j < 4; j++) bb[j] = *(const float2*)&bias[2 * tx + 64 * j];

#pragma unroll
    for (int i = 0; i < 8; i++) {
        int gm = m0 + ty * 8 + i;
        float v[8];
        float n2 = 0.f;
#pragma unroll
        for (int j = 0; j < 4; j++) {
            float2 t = unpk(acc[i][j]);
            float v0 = fmaxf(t.x + bb[j].x, 0.f);
            float v1 = fmaxf(t.y + bb[j].y, 0.f);
            v[2 * j] = v0;
            v[2 * j + 1] = v1;
            n2 += v0 * v0 + v1 * v1;
        }
#pragma unroll
        for (int o = 16; o; o >>= 1) n2 += __shfl_xor_sync(0xffffffffu, n2, o);
        bool pass = n2 > 0.5f * fmaxf(n2, EPSF);
        if (gm < M) {
            float nrm = sqrtf(n2);
            float sc = (nrm > 0.f) ? 1.f / nrm : 0.f;
            if (tx == 0) hnq[gm] = nrm;
            float2 z2 = make_float2(0.f, 0.f);
#pragma unroll
            for (int j = 0; j < 4; j++) {
                float2 hv = make_float2(v[2 * j], v[2 * j + 1]);
                *(float2*)(hq + (size_t)gm * 256 + 2 * tx + 64 * j) = hv;
                *(float2*)(aggq + (size_t)gm * 256 + 2 * tx + 64 * j) = pass ? hv : z2;
                hbq[(size_t)gm * 128 + tx + 32 * j] = pack2bf(hv.x * sc, hv.y * sc);
            }
        }
    }
}

// ---------------------------------------------------------------------------
// GEMM2 (f32x2 + prefetch): out = log_softmax(agg2 @ W2^T + b2). 128x64, K=256.
// ---------------------------------------------------------------------------
__global__ __launch_bounds__(256)
void k_gemm2_f2(const float* __restrict__ A, const float* __restrict__ W,
                const float* __restrict__ bias,
                float* __restrict__ outq, int M)
{
    __shared__ float As[16][128];
    __shared__ float Ws[16][64];
    int tid = threadIdx.x;
    int tx = tid & 15;
    int ty = tid >> 4;
    int m0 = blockIdx.x * 128;

    int lm = tid >> 2, lkq = tid & 3;
    int lgm0 = m0 + lm;
    if (lgm0 >= M) lgm0 = M - 1;
    int lgm1 = m0 + lm + 64;
    if (lgm1 >= M) lgm1 = M - 1;
    const float* Arow0 = A + (size_t)lgm0 * 256 + lkq * 4;
    const float* Arow1 = A + (size_t)lgm1 * 256 + lkq * 4;
    const float* Wrow = W + (size_t)lm * 256 + lkq * 4;

    u64 acc[8][2];
#pragma unroll
    for (int i = 0; i < 8; i++) {
        acc[i][0] = 0ull;
        acc[i][1] = 0ull;
    }

    float4 va0 = *(const float4*)Arow0;
    float4 va1 = *(const float4*)Arow1;
    float4 vw = *(const float4*)Wrow;

    for (int k0 = 0; k0 < 256; k0 += 16) {
        As[lkq * 4 + 0][lm] = va0.x;
        As[lkq * 4 + 1][lm] = va0.y;
        As[lkq * 4 + 2][lm] = va0.z;
        As[lkq * 4 + 3][lm] = va0.w;
        As[lkq * 4 + 0][lm + 64] = va1.x;
        As[lkq * 4 + 1][lm + 64] = va1.y;
        As[lkq * 4 + 2][lm + 64] = va1.z;
        As[lkq * 4 + 3][lm + 64] = va1.w;
        Ws[lkq * 4 + 0][lm] = vw.x;
        Ws[lkq * 4 + 1][lm] = vw.y;
        Ws[lkq * 4 + 2][lm] = vw.z;
        Ws[lkq * 4 + 3][lm] = vw.w;
        __syncthreads();
        if (k0 + 16 < 256) {
            va0 = *(const float4*)(Arow0 + k0 + 16);
            va1 = *(const float4*)(Arow1 + k0 + 16);
            vw = *(const float4*)(Wrow + k0 + 16);
        }
#pragma unroll
        for (int k = 0; k < 16; k++) {
            u64 rm2[8], rn[2];
#pragma unroll
            for (int i = 0; i < 8; i++) rm2[i] = dup2(As[k][ty * 8 + i]);
            rn[0] = *(const u64*)&Ws[k][2 * tx];
            rn[1] = *(const u64*)&Ws[k][2 * tx + 32];
#pragma unroll
            for (int i = 0; i < 8; i++) {
                acc[i][0] = fma2(rm2[i], rn[0], acc[i][0]);
                acc[i][1] = fma2(rm2[i], rn[1], acc[i][1]);
            }
        }
        __syncthreads();
    }

    float2 bb0 = *(const float2*)&bias[2 * tx];
    float2 bb1 = *(const float2*)&bias[2 * tx + 32];

#pragma unroll
    for (int i = 0; i < 8; i++) {
        int gm = m0 + ty * 8 + i;
        float2 t0 = unpk(acc[i][0]);
        float2 t1 = unpk(acc[i][1]);
        float v0 = t0.x + bb0.x, v1 = t0.y + bb0.y;
        float v2 = t1.x + bb1.x, v3 = t1.y + bb1.y;
        float mx = fmaxf(fmaxf(v0, v1), fmaxf(v2, v3));
#pragma unroll
        for (int o = 1; o < 16; o <<= 1)
            mx = fmaxf(mx, __shfl_xor_sync(0xffffffffu, mx, o));
        float sm = __expf(v0 - mx) + __expf(v1 - mx) +
                   __expf(v2 - mx) + __expf(v3 - mx);
#pragma unroll
        for (int o = 1; o < 16; o <<= 1)
            sm += __shfl_xor_sync(0xffffffffu, sm, o);
        float l = mx + __logf(sm);
        if (gm < M) {
            *(float2*)(outq + (size_t)gm * 64 + 2 * tx) = make_float2(v0 - l, v1 - l);
            *(float2*)(outq + (size_t)gm * 64 + 2 * tx + 32) = make_float2(v2 - l, v3 - l);
        }
    }
}

// ---------------------------------------------------------------------------
extern "C" void kernel_launch(void* const* d_in, const int* in_sizes, int n_in,
                              void* d_out, int out_size)
{
    const float* x   = (const float*)d_in[0];
    const void*  eix = d_in[1];
    const float* W1  = (const float*)d_in[2];
    const float* b1  = (const float*)d_in[3];
    const float* W2  = (const float*)d_in[4];
    const float* b2  = (const float*)d_in[5];
    float* out = (float*)d_out;

    int N = in_sizes[0] / D1;      // 50000
    int E = in_sizes[1] / 2;       // 800000
    (void)n_in; (void)out_size;

    float *agg1, *h, *agg2, *xn, *hn;
    uint4 *xb, *hb;
    cudaGetSymbolAddress((void**)&agg1, g_agg1_);
    cudaGetSymbolAddress((void**)&h,    g_h_);
    cudaGetSymbolAddress((void**)&agg2, g_agg2_);
    cudaGetSymbolAddress((void**)&xb,   g_xb_);
    cudaGetSymbolAddress((void**)&hb,   g_hb_);
    cudaGetSymbolAddress((void**)&xn,   g_xnorm);
    cudaGetSymbolAddress((void**)&hn,   g_hnorm);

    k_reset_flag<<<1, 1>>>();
    k_detect64<<<(E + 255) / 256, 256>>>(eix, E, N);

    int nodeBlocks = (N * 32 + 255) / 256;
    long long warps4 = ((long long)E + 3) / 4;
    int edgeBlocks = (int)((warps4 * 32 + 255) / 256);

    // ---- Layer 1 ----
    k_norms_init<D1><<<nodeBlocks, 256>>>(x, xn, agg1, (uint2*)xb, N);
    k_edge_q<D1><<<edgeBlocks, 256>>>(x, xb, xn, eix, agg1, E);
    k_gemm1_f2<<<(N + 63) / 64, 256>>>(agg1, W1, b1, h, (unsigned*)hb, hn, agg2, N);

    // ---- Layer 2 ----
    k_edge_q<D2><<<edgeBlocks, 256>>>(h, hb, hn, eix, agg2, E);
    k_gemm2_f2<<<(N + 127) / 128, 256>>>(agg2, W2, b2, out, N);
}